// round 1
// baseline (speedup 1.0000x reference)
#include <cuda_runtime.h>
#include <math.h>

// Problem constants
#define Bq  2
#define Sq  2048
#define Dq  1024
#define Hq  16
#define HDq 64

// Scratch (static device allocations are allowed)
__device__ float g_qkv[(size_t)Bq * Sq * 3 * Dq];   // (B,S,3D) = 50.3 MB
__device__ float g_vals[(size_t)Bq * Sq * Dq];      // (B,S,D)  = 16.8 MB

// ---------------------------------------------------------------------------
// C[M,N] = A[M,K] @ W[N,K]^T + bias[N]
// BM=BN=128, BK=16, 256 threads, 8x8 per thread.
// ---------------------------------------------------------------------------
__global__ void __launch_bounds__(256)
sgemm_nt_bias(int M, int N, int K,
              const float* __restrict__ A,
              const float* __restrict__ W,
              const float* __restrict__ bias,
              float* __restrict__ C)
{
    constexpr int BM = 128, BN = 128, BK = 16;
    __shared__ float As[BK][BM + 1];
    __shared__ float Ws[BK][BN + 1];

    const int tid = threadIdx.x;
    const int m0 = blockIdx.y * BM;
    const int n0 = blockIdx.x * BN;

    const int lr  = tid >> 2;          // 0..63
    const int lc4 = (tid & 3) << 2;    // 0,4,8,12

    float acc[8][8];
#pragma unroll
    for (int i = 0; i < 8; i++)
#pragma unroll
        for (int j = 0; j < 8; j++) acc[i][j] = 0.0f;

    const int tr = (tid >> 4) << 3;    // 0..120
    const int tc = (tid & 15) << 3;    // 0..120

    for (int k0 = 0; k0 < K; k0 += BK) {
#pragma unroll
        for (int h2 = 0; h2 < 2; h2++) {
            const int r = lr + h2 * 64;
            float4 av = *(const float4*)(A + (size_t)(m0 + r) * K + k0 + lc4);
            As[lc4 + 0][r] = av.x; As[lc4 + 1][r] = av.y;
            As[lc4 + 2][r] = av.z; As[lc4 + 3][r] = av.w;
            float4 wv = *(const float4*)(W + (size_t)(n0 + r) * K + k0 + lc4);
            Ws[lc4 + 0][r] = wv.x; Ws[lc4 + 1][r] = wv.y;
            Ws[lc4 + 2][r] = wv.z; Ws[lc4 + 3][r] = wv.w;
        }
        __syncthreads();

#pragma unroll
        for (int k = 0; k < BK; k++) {
            float ra[8], rb[8];
#pragma unroll
            for (int i = 0; i < 8; i++) ra[i] = As[k][tr + i];
#pragma unroll
            for (int j = 0; j < 8; j++) rb[j] = Ws[k][tc + j];
#pragma unroll
            for (int i = 0; i < 8; i++)
#pragma unroll
                for (int j = 0; j < 8; j++)
                    acc[i][j] = fmaf(ra[i], rb[j], acc[i][j]);
        }
        __syncthreads();
    }

#pragma unroll
    for (int i = 0; i < 8; i++) {
#pragma unroll
        for (int j4 = 0; j4 < 8; j4 += 4) {
            float4 o;
            o.x = acc[i][j4 + 0] + bias[n0 + tc + j4 + 0];
            o.y = acc[i][j4 + 1] + bias[n0 + tc + j4 + 1];
            o.z = acc[i][j4 + 2] + bias[n0 + tc + j4 + 2];
            o.w = acc[i][j4 + 3] + bias[n0 + tc + j4 + 3];
            *(float4*)(C + (size_t)(m0 + tr + i) * N + n0 + tc + j4) = o;
        }
    }
}

// ---------------------------------------------------------------------------
// Flash attention, fp32. Grid (S/64, H, B), 256 threads.
// Q,K,V read from qkv (B,S,3D): head h uses cols [h*192, h*192+192): q,k,v.
// Output written as (B,S,D) with d = h*64 + hd.
// Dynamic smem: Qs[d][i], Ks[d][j], Vs[j][d], Ps[j][i], each 64x65 floats.
// ---------------------------------------------------------------------------
__global__ void __launch_bounds__(256)
flash_attn(const float* __restrict__ qkv,
           const float* __restrict__ mask,
           float* __restrict__ out)
{
    extern __shared__ float sm[];
    float* Qs = sm;                 // [d*65 + i]
    float* Ks = sm + 64 * 65;       // [d*65 + j]
    float* Vs = sm + 2 * 64 * 65;   // [j*65 + d]
    float* Ps = sm + 3 * 64 * 65;   // [j*65 + i]

    const int tid = threadIdx.x;
    const int tx = tid & 15;        // 0..15 -> 4 cols each
    const int ty = tid >> 4;        // 0..15 -> 4 rows each
    const int q0 = blockIdx.x * 64;
    const int h  = blockIdx.y;
    const int b  = blockIdx.z;
    const float scale = 0.125f;     // 1/sqrt(64)

    const float* base = qkv + (size_t)b * Sq * (3 * Dq) + (size_t)h * (3 * HDq);

    // Load Q tile, transposed: Qs[d][i]
#pragma unroll
    for (int rr = 0; rr < 4; rr++) {
        const int i  = (tid >> 4) + rr * 16;
        const int d4 = (tid & 15) << 2;
        float4 v = *(const float4*)(base + (size_t)(q0 + i) * (3 * Dq) + d4);
        Qs[(d4 + 0) * 65 + i] = v.x;
        Qs[(d4 + 1) * 65 + i] = v.y;
        Qs[(d4 + 2) * 65 + i] = v.z;
        Qs[(d4 + 3) * 65 + i] = v.w;
    }

    float mrow[4], lrow[4], O[4][4];
#pragma unroll
    for (int a = 0; a < 4; a++) {
        mrow[a] = -INFINITY;
        lrow[a] = 0.0f;
#pragma unroll
        for (int c = 0; c < 4; c++) O[a][c] = 0.0f;
    }

    for (int kt = 0; kt < Sq / 64; kt++) {
        const int k0 = kt * 64;
        __syncthreads();   // prev PV done (and Q visible on first iter)

        // Load K (transposed) and V tiles
#pragma unroll
        for (int rr = 0; rr < 4; rr++) {
            const int j  = (tid >> 4) + rr * 16;
            const int d4 = (tid & 15) << 2;
            float4 kv = *(const float4*)(base + 64 + (size_t)(k0 + j) * (3 * Dq) + d4);
            Ks[(d4 + 0) * 65 + j] = kv.x;
            Ks[(d4 + 1) * 65 + j] = kv.y;
            Ks[(d4 + 2) * 65 + j] = kv.z;
            Ks[(d4 + 3) * 65 + j] = kv.w;
            float4 vv = *(const float4*)(base + 128 + (size_t)(k0 + j) * (3 * Dq) + d4);
            Vs[j * 65 + d4 + 0] = vv.x;
            Vs[j * 65 + d4 + 1] = vv.y;
            Vs[j * 65 + d4 + 2] = vv.z;
            Vs[j * 65 + d4 + 3] = vv.w;
        }
        __syncthreads();

        // S = Q K^T  (4x4 per thread)
        float Sv[4][4];
#pragma unroll
        for (int a = 0; a < 4; a++)
#pragma unroll
            for (int c = 0; c < 4; c++) Sv[a][c] = 0.0f;

#pragma unroll
        for (int d = 0; d < 64; d++) {
            float qa[4], kb[4];
#pragma unroll
            for (int a = 0; a < 4; a++) qa[a] = Qs[d * 65 + ty * 4 + a];
#pragma unroll
            for (int c = 0; c < 4; c++) kb[c] = Ks[d * 65 + tx * 4 + c];
#pragma unroll
            for (int a = 0; a < 4; a++)
#pragma unroll
                for (int c = 0; c < 4; c++)
                    Sv[a][c] = fmaf(qa[a], kb[c], Sv[a][c]);
        }

        // scale + mask
#pragma unroll
        for (int a = 0; a < 4; a++) {
            const float* mrp = mask + (size_t)(q0 + ty * 4 + a) * Sq + k0 + tx * 4;
#pragma unroll
            for (int c = 0; c < 4; c++)
                Sv[a][c] = Sv[a][c] * scale + mrp[c];
        }

        // Online softmax per row (16 lanes per row-group share via shfl)
#pragma unroll
        for (int a = 0; a < 4; a++) {
            float mx = fmaxf(fmaxf(Sv[a][0], Sv[a][1]), fmaxf(Sv[a][2], Sv[a][3]));
#pragma unroll
            for (int off = 1; off < 16; off <<= 1)
                mx = fmaxf(mx, __shfl_xor_sync(0xffffffffu, mx, off));
            const float mnew = fmaxf(mrow[a], mx);
            const float alpha = __expf(mrow[a] - mnew);
            float rs = 0.0f;
#pragma unroll
            for (int c = 0; c < 4; c++) {
                Sv[a][c] = __expf(Sv[a][c] - mnew);
                rs += Sv[a][c];
            }
#pragma unroll
            for (int off = 1; off < 16; off <<= 1)
                rs += __shfl_xor_sync(0xffffffffu, rs, off);
            lrow[a] = lrow[a] * alpha + rs;
            mrow[a] = mnew;
#pragma unroll
            for (int c = 0; c < 4; c++) O[a][c] *= alpha;
            // stash P transposed: Ps[j][i]
#pragma unroll
            for (int c = 0; c < 4; c++)
                Ps[(tx * 4 + c) * 65 + ty * 4 + a] = Sv[a][c];
        }
        __syncthreads();

        // O += P V
#pragma unroll
        for (int j = 0; j < 64; j++) {
            float pa[4], vb[4];
#pragma unroll
            for (int a = 0; a < 4; a++) pa[a] = Ps[j * 65 + ty * 4 + a];
#pragma unroll
            for (int c = 0; c < 4; c++) vb[c] = Vs[j * 65 + tx * 4 + c];
#pragma unroll
            for (int a = 0; a < 4; a++)
#pragma unroll
                for (int c = 0; c < 4; c++)
                    O[a][c] = fmaf(pa[a], vb[c], O[a][c]);
        }
    }

    // Epilogue: normalize and store to (B,S,D) layout
#pragma unroll
    for (int a = 0; a < 4; a++) {
        const float inv = 1.0f / lrow[a];
        const int row = q0 + ty * 4 + a;
        float4 o;
        o.x = O[a][0] * inv; o.y = O[a][1] * inv;
        o.z = O[a][2] * inv; o.w = O[a][3] * inv;
        *(float4*)(out + (size_t)b * Sq * Dq + (size_t)row * Dq + h * HDq + tx * 4) = o;
    }
}

// ---------------------------------------------------------------------------
extern "C" void kernel_launch(void* const* d_in, const int* in_sizes, int n_in,
                              void* d_out, int out_size)
{
    const float* x    = (const float*)d_in[0];
    const float* mask = (const float*)d_in[1];
    const float* Wqkv = (const float*)d_in[2];
    const float* bqkv = (const float*)d_in[3];
    const float* Wo   = (const float*)d_in[4];
    const float* bo   = (const float*)d_in[5];
    float* out = (float*)d_out;

    float* qkv  = nullptr;
    float* vals = nullptr;
    cudaGetSymbolAddress((void**)&qkv,  g_qkv);
    cudaGetSymbolAddress((void**)&vals, g_vals);

    // 1) QKV projection: (B*S, D) @ Wqkv^T -> (B*S, 3D)
    {
        dim3 grid((3 * Dq) / 128, (Bq * Sq) / 128);
        sgemm_nt_bias<<<grid, 256>>>(Bq * Sq, 3 * Dq, Dq, x, Wqkv, bqkv, qkv);
    }

    // 2) Flash attention
    {
        const int smem = 4 * 64 * 65 * (int)sizeof(float);  // 66560 B
        cudaFuncSetAttribute(flash_attn,
                             cudaFuncAttributeMaxDynamicSharedMemorySize, smem);
        dim3 grid(Sq / 64, Hq, Bq);
        flash_attn<<<grid, 256, smem>>>(qkv, mask, vals);
    }

    // 3) Output projection: (B*S, D) @ Wo^T -> (B*S, D)
    {
        dim3 grid(Dq / 128, (Bq * Sq) / 128);
        sgemm_nt_bias<<<grid, 256>>>(Bq * Sq, Dq, Dq, vals, Wo, bo, out);
    }
}

// round 2
// speedup vs baseline: 3.1146x; 3.1146x over previous
#include <cuda_runtime.h>
#include <math.h>
#include <stdint.h>

// Problem constants
#define Bq  2
#define Sq  2048
#define Dq  1024
#define Hq  16
#define HDq 64

__device__ float g_qkv[(size_t)Bq * Sq * 3 * Dq];   // (B,S,3D)
__device__ float g_vals[(size_t)Bq * Sq * Dq];      // (B,S,D)

// ---------------------------------------------------------------------------
// tf32 helpers
// ---------------------------------------------------------------------------
__device__ __forceinline__ uint32_t f2tf32(float x) {
    uint32_t r;
    asm("cvt.rna.tf32.f32 %0, %1;" : "=r"(r) : "f"(x));
    return r;
}

__device__ __forceinline__ void mma_tf32(float c[4],
                                         uint32_t a0, uint32_t a1, uint32_t a2, uint32_t a3,
                                         uint32_t b0, uint32_t b1) {
    asm volatile(
        "mma.sync.aligned.m16n8k8.row.col.f32.tf32.tf32.f32 "
        "{%0,%1,%2,%3}, {%4,%5,%6,%7}, {%8,%9}, {%0,%1,%2,%3};"
        : "+f"(c[0]), "+f"(c[1]), "+f"(c[2]), "+f"(c[3])
        : "r"(a0), "r"(a1), "r"(a2), "r"(a3), "r"(b0), "r"(b1));
}

// ---------------------------------------------------------------------------
// tf32 GEMM: C[M,N] = A[M,K] @ W[N,K]^T + bias[N]
// BM=128, BN=128, BK=32. 256 threads = 8 warps in 2x4; warp tile 64x32.
// ---------------------------------------------------------------------------
__global__ void __launch_bounds__(256)
gemm_tf32_nt_bias(int M, int N, int K,
                  const float* __restrict__ A,
                  const float* __restrict__ W,
                  const float* __restrict__ bias,
                  float* __restrict__ C)
{
    constexpr int BK = 32, PITCH = 36;
    __shared__ uint32_t As[128][PITCH];
    __shared__ uint32_t Ws[128][PITCH];

    const int tid  = threadIdx.x;
    const int lane = tid & 31;
    const int w    = tid >> 5;
    const int wr   = w >> 2;      // 0..1
    const int wc   = w & 3;       // 0..3
    const int m0   = blockIdx.y * 128;
    const int n0   = blockIdx.x * 128;

    const int g  = lane >> 2;     // groupID 0..7
    const int tq = lane & 3;      // threadID in quad 0..3

    float acc[4][4][4];
#pragma unroll
    for (int i = 0; i < 4; i++)
#pragma unroll
        for (int j = 0; j < 4; j++)
#pragma unroll
            for (int e = 0; e < 4; e++) acc[i][j][e] = 0.0f;

    const int lrow = tid >> 3;          // 0..31
    const int lc4  = (tid & 7) << 2;    // 0..28

    for (int k0 = 0; k0 < K; k0 += BK) {
#pragma unroll
        for (int rr = 0; rr < 4; rr++) {
            const int r = lrow + rr * 32;
            float4 av = *(const float4*)(A + (size_t)(m0 + r) * K + k0 + lc4);
            As[r][lc4 + 0] = f2tf32(av.x); As[r][lc4 + 1] = f2tf32(av.y);
            As[r][lc4 + 2] = f2tf32(av.z); As[r][lc4 + 3] = f2tf32(av.w);
            float4 wv = *(const float4*)(W + (size_t)(n0 + r) * K + k0 + lc4);
            Ws[r][lc4 + 0] = f2tf32(wv.x); Ws[r][lc4 + 1] = f2tf32(wv.y);
            Ws[r][lc4 + 2] = f2tf32(wv.z); Ws[r][lc4 + 3] = f2tf32(wv.w);
        }
        __syncthreads();

#pragma unroll
        for (int ks = 0; ks < 4; ks++) {
            const int kk = ks * 8;
            uint32_t af[4][4];
#pragma unroll
            for (int mi = 0; mi < 4; mi++) {
                const int rb = wr * 64 + mi * 16;
                af[mi][0] = As[rb + g    ][kk + tq    ];
                af[mi][1] = As[rb + g + 8][kk + tq    ];
                af[mi][2] = As[rb + g    ][kk + tq + 4];
                af[mi][3] = As[rb + g + 8][kk + tq + 4];
            }
            uint32_t bf[4][2];
#pragma unroll
            for (int ni = 0; ni < 4; ni++) {
                const int cb = wc * 32 + ni * 8;
                bf[ni][0] = Ws[cb + g][kk + tq    ];
                bf[ni][1] = Ws[cb + g][kk + tq + 4];
            }
#pragma unroll
            for (int mi = 0; mi < 4; mi++)
#pragma unroll
                for (int ni = 0; ni < 4; ni++)
                    mma_tf32(acc[mi][ni],
                             af[mi][0], af[mi][1], af[mi][2], af[mi][3],
                             bf[ni][0], bf[ni][1]);
        }
        __syncthreads();
    }

    // Epilogue: direct global stores with bias
#pragma unroll
    for (int mi = 0; mi < 4; mi++) {
        const int r0 = m0 + wr * 64 + mi * 16 + g;
#pragma unroll
        for (int ni = 0; ni < 4; ni++) {
            const int c = n0 + wc * 32 + ni * 8 + 2 * tq;
            const float b0v = bias[c], b1v = bias[c + 1];
            float2 o0 = make_float2(acc[mi][ni][0] + b0v, acc[mi][ni][1] + b1v);
            float2 o1 = make_float2(acc[mi][ni][2] + b0v, acc[mi][ni][3] + b1v);
            *(float2*)(C + (size_t)r0 * N + c)       = o0;
            *(float2*)(C + (size_t)(r0 + 8) * N + c) = o1;
        }
    }
}

// ---------------------------------------------------------------------------
// Flash attention, tf32 tensor cores. Grid (S/64, H, B), 128 threads (4 warps).
// Each warp owns 16 query rows. Q/K/P pitch 68, V pitch 72 (bank-conflict-free
// fragment loads).
// ---------------------------------------------------------------------------
#define QP 68
#define VP 72

__global__ void __launch_bounds__(128)
flash_attn_tf32(const float* __restrict__ qkv,
                const float* __restrict__ mask,
                float* __restrict__ out)
{
    extern __shared__ uint32_t sm[];
    uint32_t* Qs = sm;                       // [64][QP]
    uint32_t* Ks = sm + 64 * QP;             // [64][QP]
    uint32_t* Ps = sm + 2 * 64 * QP;         // [64][QP]  (q rows x key cols)
    uint32_t* Vs = sm + 3 * 64 * QP;         // [64][VP]  (key rows x hd cols)

    const int tid  = threadIdx.x;
    const int lane = tid & 31;
    const int wid  = tid >> 5;     // 0..3 -> q rows [wid*16, +16)
    const int g    = lane >> 2;    // 0..7
    const int tq   = lane & 3;     // 0..3

    const int q0 = blockIdx.x * 64;
    const int h  = blockIdx.y;
    const int b  = blockIdx.z;
    const float scale = 0.125f;

    const float* base = qkv + (size_t)b * Sq * (3 * Dq) + (size_t)h * (3 * HDq);

    // Load Q tile (64 x 64) as tf32
#pragma unroll
    for (int rr = 0; rr < 8; rr++) {
        const int r  = (tid >> 4) + rr * 8;
        const int c4 = (tid & 15) << 2;
        float4 v = *(const float4*)(base + (size_t)(q0 + r) * (3 * Dq) + c4);
        Qs[r * QP + c4 + 0] = f2tf32(v.x);
        Qs[r * QP + c4 + 1] = f2tf32(v.y);
        Qs[r * QP + c4 + 2] = f2tf32(v.z);
        Qs[r * QP + c4 + 3] = f2tf32(v.w);
    }

    float Oacc[8][4];
#pragma unroll
    for (int ni = 0; ni < 8; ni++)
#pragma unroll
        for (int e = 0; e < 4; e++) Oacc[ni][e] = 0.0f;
    float mrow0 = -INFINITY, mrow1 = -INFINITY;
    float lrow0 = 0.0f, lrow1 = 0.0f;

    const int r0 = wid * 16 + g;   // this thread's first q row (within tile)
    const int r1 = r0 + 8;

    for (int kt = 0; kt < Sq / 64; kt++) {
        const int k0t = kt * 64;
        __syncthreads();   // K/V/P buffers free (prev PV done); Q visible after 1st

        // Load K and V tiles
#pragma unroll
        for (int rr = 0; rr < 8; rr++) {
            const int r  = (tid >> 4) + rr * 8;
            const int c4 = (tid & 15) << 2;
            float4 kv = *(const float4*)(base + 64 + (size_t)(k0t + r) * (3 * Dq) + c4);
            Ks[r * QP + c4 + 0] = f2tf32(kv.x);
            Ks[r * QP + c4 + 1] = f2tf32(kv.y);
            Ks[r * QP + c4 + 2] = f2tf32(kv.z);
            Ks[r * QP + c4 + 3] = f2tf32(kv.w);
            float4 vv = *(const float4*)(base + 128 + (size_t)(k0t + r) * (3 * Dq) + c4);
            Vs[r * VP + c4 + 0] = f2tf32(vv.x);
            Vs[r * VP + c4 + 1] = f2tf32(vv.y);
            Vs[r * VP + c4 + 2] = f2tf32(vv.z);
            Vs[r * VP + c4 + 3] = f2tf32(vv.w);
        }
        __syncthreads();

        // S = Q K^T : warp computes 16 x 64 (8 n-tiles)
        float Sacc[8][4];
#pragma unroll
        for (int ni = 0; ni < 8; ni++)
#pragma unroll
            for (int e = 0; e < 4; e++) Sacc[ni][e] = 0.0f;

#pragma unroll
        for (int ks = 0; ks < 8; ks++) {
            const int kk = ks * 8;
            const int mb = wid * 16;
            uint32_t a0 = Qs[(mb + g)     * QP + kk + tq];
            uint32_t a1 = Qs[(mb + g + 8) * QP + kk + tq];
            uint32_t a2 = Qs[(mb + g)     * QP + kk + tq + 4];
            uint32_t a3 = Qs[(mb + g + 8) * QP + kk + tq + 4];
#pragma unroll
            for (int ni = 0; ni < 8; ni++) {
                const int nb = ni * 8;
                uint32_t b0 = Ks[(nb + g) * QP + kk + tq];
                uint32_t b1 = Ks[(nb + g) * QP + kk + tq + 4];
                mma_tf32(Sacc[ni], a0, a1, a2, a3, b0, b1);
            }
        }

        // scale + mask + online softmax (rows r0, r1; cols 8*ni + 2*tq {,+1})
        float p0[8][2], p1[8][2];
        float rmax0 = -INFINITY, rmax1 = -INFINITY;
#pragma unroll
        for (int ni = 0; ni < 8; ni++) {
            const int c = ni * 8 + 2 * tq;
            float2 mk0 = *(const float2*)(mask + (size_t)(q0 + r0) * Sq + k0t + c);
            float2 mk1 = *(const float2*)(mask + (size_t)(q0 + r1) * Sq + k0t + c);
            p0[ni][0] = Sacc[ni][0] * scale + mk0.x;
            p0[ni][1] = Sacc[ni][1] * scale + mk0.y;
            p1[ni][0] = Sacc[ni][2] * scale + mk1.x;
            p1[ni][1] = Sacc[ni][3] * scale + mk1.y;
            rmax0 = fmaxf(rmax0, fmaxf(p0[ni][0], p0[ni][1]));
            rmax1 = fmaxf(rmax1, fmaxf(p1[ni][0], p1[ni][1]));
        }
        // reduce across quad (lanes sharing g)
#pragma unroll
        for (int off = 1; off < 4; off <<= 1) {
            rmax0 = fmaxf(rmax0, __shfl_xor_sync(0xffffffffu, rmax0, off));
            rmax1 = fmaxf(rmax1, __shfl_xor_sync(0xffffffffu, rmax1, off));
        }
        const float mnew0 = fmaxf(mrow0, rmax0);
        const float mnew1 = fmaxf(mrow1, rmax1);
        const float alpha0 = __expf(mrow0 - mnew0);
        const float alpha1 = __expf(mrow1 - mnew1);
        float rs0 = 0.0f, rs1 = 0.0f;
#pragma unroll
        for (int ni = 0; ni < 8; ni++) {
            p0[ni][0] = __expf(p0[ni][0] - mnew0);
            p0[ni][1] = __expf(p0[ni][1] - mnew0);
            p1[ni][0] = __expf(p1[ni][0] - mnew1);
            p1[ni][1] = __expf(p1[ni][1] - mnew1);
            rs0 += p0[ni][0] + p0[ni][1];
            rs1 += p1[ni][0] + p1[ni][1];
        }
#pragma unroll
        for (int off = 1; off < 4; off <<= 1) {
            rs0 += __shfl_xor_sync(0xffffffffu, rs0, off);
            rs1 += __shfl_xor_sync(0xffffffffu, rs1, off);
        }
        lrow0 = lrow0 * alpha0 + rs0;
        lrow1 = lrow1 * alpha1 + rs1;
        mrow0 = mnew0;
        mrow1 = mnew1;
#pragma unroll
        for (int ni = 0; ni < 8; ni++) {
            Oacc[ni][0] *= alpha0; Oacc[ni][1] *= alpha0;
            Oacc[ni][2] *= alpha1; Oacc[ni][3] *= alpha1;
        }
        // stash P: Ps[q_row][key_col] as tf32
        const int qr0 = wid * 16 + g;
#pragma unroll
        for (int ni = 0; ni < 8; ni++) {
            const int c = ni * 8 + 2 * tq;
            uint2 s0 = make_uint2(f2tf32(p0[ni][0]), f2tf32(p0[ni][1]));
            uint2 s1 = make_uint2(f2tf32(p1[ni][0]), f2tf32(p1[ni][1]));
            *(uint2*)(Ps + (qr0)     * QP + c) = s0;
            *(uint2*)(Ps + (qr0 + 8) * QP + c) = s1;
        }
        __syncthreads();   // Ps visible to all warps of this warp's rows (self) — and orders Vs reads

        // O += P V : A = Ps (16 x 64 keys), B = Vs (keys x hd)
#pragma unroll
        for (int ks = 0; ks < 8; ks++) {
            const int kk = ks * 8;
            const int mb = wid * 16;
            uint32_t a0 = Ps[(mb + g)     * QP + kk + tq];
            uint32_t a1 = Ps[(mb + g + 8) * QP + kk + tq];
            uint32_t a2 = Ps[(mb + g)     * QP + kk + tq + 4];
            uint32_t a3 = Ps[(mb + g + 8) * QP + kk + tq + 4];
#pragma unroll
            for (int ni = 0; ni < 8; ni++) {
                const int nb = ni * 8;
                uint32_t b0 = Vs[(kk + tq)     * VP + nb + g];
                uint32_t b1 = Vs[(kk + tq + 4) * VP + nb + g];
                mma_tf32(Oacc[ni], a0, a1, a2, a3, b0, b1);
            }
        }
    }

    // Epilogue
    const float inv0 = 1.0f / lrow0;
    const float inv1 = 1.0f / lrow1;
    float* obase = out + (size_t)b * Sq * Dq + (size_t)h * HDq;
#pragma unroll
    for (int ni = 0; ni < 8; ni++) {
        const int c = ni * 8 + 2 * tq;
        float2 o0 = make_float2(Oacc[ni][0] * inv0, Oacc[ni][1] * inv0);
        float2 o1 = make_float2(Oacc[ni][2] * inv1, Oacc[ni][3] * inv1);
        *(float2*)(obase + (size_t)(q0 + r0) * Dq + c) = o0;
        *(float2*)(obase + (size_t)(q0 + r1) * Dq + c) = o1;
    }
}

// ---------------------------------------------------------------------------
extern "C" void kernel_launch(void* const* d_in, const int* in_sizes, int n_in,
                              void* d_out, int out_size)
{
    const float* x    = (const float*)d_in[0];
    const float* mask = (const float*)d_in[1];
    const float* Wqkv = (const float*)d_in[2];
    const float* bqkv = (const float*)d_in[3];
    const float* Wo   = (const float*)d_in[4];
    const float* bo   = (const float*)d_in[5];
    float* out = (float*)d_out;

    float* qkv  = nullptr;
    float* vals = nullptr;
    cudaGetSymbolAddress((void**)&qkv,  g_qkv);
    cudaGetSymbolAddress((void**)&vals, g_vals);

    // 1) QKV projection
    {
        dim3 grid((3 * Dq) / 128, (Bq * Sq) / 128);
        gemm_tf32_nt_bias<<<grid, 256>>>(Bq * Sq, 3 * Dq, Dq, x, Wqkv, bqkv, qkv);
    }

    // 2) Flash attention (tf32 mma)
    {
        const int smem = (3 * 64 * QP + 64 * VP) * (int)sizeof(uint32_t); // 70656 B
        static bool configured = false;
        if (!configured) {
            cudaFuncSetAttribute(flash_attn_tf32,
                                 cudaFuncAttributeMaxDynamicSharedMemorySize, smem);
            configured = true;
        }
        dim3 grid(Sq / 64, Hq, Bq);
        flash_attn_tf32<<<grid, 128, smem>>>(qkv, mask, vals);
    }

    // 3) Output projection
    {
        dim3 grid(Dq / 128, (Bq * Sq) / 128);
        gemm_tf32_nt_bias<<<grid, 256>>>(Bq * Sq, Dq, Dq, vals, Wo, bo, out);
    }
}